// round 1
// baseline (speedup 1.0000x reference)
#include <cuda_runtime.h>

// DeltaEncoder: delta -> BatchNorm(1ch, eval) -> Linear(1,64) broadcast ->
// LIF scan over the 64 output channels (per the reference, scan axis is O).
// Output [B, O, F, T] float32 spikes (0/1).
//
// B=32, T=512, F=64, O=64. Output = 268 MB => HBM-write-bound.
// One thread handles 4 consecutive t; writes float4 per channel o.

#define BB 32
#define TT 512
#define FF 64
#define OO 64

__global__ __launch_bounds__(256)
void delta_encoder_kernel(const float* __restrict__ in,     // [B,T,F]
                          const float* __restrict__ enc_w,  // [O]
                          const float* __restrict__ enc_b,  // [O]
                          const float* __restrict__ bn_w,
                          const float* __restrict__ bn_b,
                          const float* __restrict__ bn_mean,
                          const float* __restrict__ bn_var,
                          float* __restrict__ out)          // [B,O,F,T]
{
    __shared__ float sw[OO];
    __shared__ float sb[OO];
    int tid = threadIdx.x;
    if (tid < OO) {
        sw[tid] = enc_w[tid];
        sb[tid] = enc_b[tid];
    }
    __syncthreads();

    int idx = blockIdx.x * blockDim.x + tid;       // 0 .. B*F*T/4-1
    const int T4 = TT / 4;
    int t4 = idx % T4;
    int f  = (idx / T4) % FF;
    int b  = idx / (T4 * FF);
    int t  = t4 * 4;

    // BatchNorm constants (single channel, eval mode)
    float inv  = bn_w[0] * rsqrtf(bn_var[0] + 1e-5f);
    float mean = bn_mean[0];
    float beta = bn_b[0];

    // Load inputs t-1 .. t+3 (stride F in memory)
    const float* ip = in + ((long)b * TT + t) * FF + f;
    float xi0 = (t == 0) ? ip[0] : ip[-FF];   // makes delta at t=0 equal 0
    float xi1 = ip[0];
    float xi2 = ip[FF];
    float xi3 = ip[2 * FF];
    float xi4 = ip[3 * FF];

    float x0 = ((xi1 - xi0) - mean) * inv + beta;
    float x1 = ((xi2 - xi1) - mean) * inv + beta;
    float x2 = ((xi3 - xi2) - mean) * inv + beta;
    float x3 = ((xi4 - xi3) - mean) * inv + beta;

    float v0 = 0.f, v1 = 0.f, v2 = 0.f, v3 = 0.f;

    // out[((b*O + o)*F + f)*T + t], advance o => stride F*T floats
    float4* op = (float4*)(out + (((long)b * OO) * FF + f) * (long)TT + t);
    const long stride4 = (long)FF * TT / 4;   // in float4 units

    #pragma unroll 4
    for (int o = 0; o < OO; o++) {
        float w  = sw[o];
        float bo = sb[o];

        float h0 = 0.5f * (v0 + fmaf(x0, w, bo));
        float h1 = 0.5f * (v1 + fmaf(x1, w, bo));
        float h2 = 0.5f * (v2 + fmaf(x2, w, bo));
        float h3 = 0.5f * (v3 + fmaf(x3, w, bo));

        float s0 = (h0 >= 1.0f) ? 1.0f : 0.0f;
        float s1 = (h1 >= 1.0f) ? 1.0f : 0.0f;
        float s2 = (h2 >= 1.0f) ? 1.0f : 0.0f;
        float s3 = (h3 >= 1.0f) ? 1.0f : 0.0f;

        v0 = (h0 >= 1.0f) ? 0.0f : h0;
        v1 = (h1 >= 1.0f) ? 0.0f : h1;
        v2 = (h2 >= 1.0f) ? 0.0f : h2;
        v3 = (h3 >= 1.0f) ? 0.0f : h3;

        *op = make_float4(s0, s1, s2, s3);
        op += stride4;
    }
}

extern "C" void kernel_launch(void* const* d_in, const int* in_sizes, int n_in,
                              void* d_out, int out_size) {
    const float* in      = (const float*)d_in[0];
    const float* enc_w   = (const float*)d_in[1];
    const float* enc_b   = (const float*)d_in[2];
    const float* bn_w    = (const float*)d_in[3];
    const float* bn_b    = (const float*)d_in[4];
    const float* bn_mean = (const float*)d_in[5];
    const float* bn_var  = (const float*)d_in[6];
    float* out = (float*)d_out;

    int total = BB * FF * (TT / 4);       // 524288 / 2 = 262144 threads
    int block = 256;
    int grid  = (total + block - 1) / block;
    delta_encoder_kernel<<<grid, block>>>(in, enc_w, enc_b, bn_w, bn_b,
                                          bn_mean, bn_var, out);
}